// round 1
// baseline (speedup 1.0000x reference)
#include <cuda_runtime.h>
#include <cub/cub.cuh>
#include <cstdint>

// Problem constants (B=4,H=8,S=1024,D=64)
#define BH 32
#define S 1024
#define D 64
#define N_ELE (BH * S * S)          // 33554432 = 2^25
#define IDX_MASK 0x01FFFFFFu
#define FLAG_NEG 0x80000000u
#define FLAG_ZERO 0x40000000u

// Static device scratch (allocation-free rule: __device__ globals only)
__device__ unsigned g_keysA[N_ELE];
__device__ unsigned g_keysB[N_ELE];
__device__ unsigned g_valsA[N_ELE];
__device__ unsigned g_valsB[N_ELE];
__device__ float    g_w[N_ELE];
__device__ float    g_invq[BH * S];
__device__ float    g_invk[BH * S];
__device__ unsigned char g_temp[512u * 1024u * 1024u];

// ---------------------------------------------------------------------------
// Stage 1: inverse lengths  inv = 1/(sqrt(sum sq)+1e-5), one warp per row
// ---------------------------------------------------------------------------
__global__ void norms_kernel(const float* __restrict__ q, const float* __restrict__ k) {
    int warp = (blockIdx.x * blockDim.x + threadIdx.x) >> 5;
    int lane = threadIdx.x & 31;
    if (warp >= 2 * BH * S) return;
    bool is_q = warp < BH * S;
    int row = is_q ? warp : warp - BH * S;
    const float* p = (is_q ? q : k) + (size_t)row * D;
    float v0 = p[lane], v1 = p[lane + 32];
    float s = v0 * v0 + v1 * v1;
    #pragma unroll
    for (int o = 16; o; o >>= 1) s += __shfl_xor_sync(0xffffffffu, s, o);
    if (lane == 0) (is_q ? g_invq : g_invk)[row] = 1.0f / (sqrtf(s) + 1e-5f);
}

// ---------------------------------------------------------------------------
// Stage 2: QK^T (fp32), epilogue emits sort keys (abs bits) + payload (idx|flags)
// 64x64 tile, 256 threads, 4x4 micro-tile, transposed smem (pitch 65)
// ---------------------------------------------------------------------------
__global__ void qk_kernel(const float* __restrict__ Q, const float* __restrict__ K) {
    __shared__ float Qs[64][65];   // Qs[d][r]
    __shared__ float Ks[64][65];   // Ks[d][c]
    int bh = blockIdx.z;
    int i0 = blockIdx.y * 64;
    int j0 = blockIdx.x * 64;
    const float* Qb = Q + ((size_t)bh * S + i0) * D;
    const float* Kb = K + ((size_t)bh * S + j0) * D;
    int tid = threadIdx.x;

    #pragma unroll
    for (int l = 0; l < 16; l++) {
        int idx = tid + l * 256;          // 0..4095
        int r = idx >> 6, d = idx & 63;
        Qs[d][r] = Qb[(size_t)r * D + d];
        Ks[d][r] = Kb[(size_t)r * D + d];
    }
    __syncthreads();

    int tx = tid & 15, ty = tid >> 4;
    float acc[4][4] = {};
    #pragma unroll 8
    for (int d = 0; d < 64; d++) {
        float a[4], b[4];
        #pragma unroll
        for (int u = 0; u < 4; u++) a[u] = Qs[d][ty * 4 + u];
        #pragma unroll
        for (int u = 0; u < 4; u++) b[u] = Ks[d][tx * 4 + u];
        #pragma unroll
        for (int r = 0; r < 4; r++)
            #pragma unroll
            for (int u = 0; u < 4; u++)
                acc[r][u] += a[r] * b[u];
    }

    float iq[4], ik[4];
    #pragma unroll
    for (int u = 0; u < 4; u++) {
        iq[u] = g_invq[bh * S + i0 + ty * 4 + u];
        ik[u] = g_invk[bh * S + j0 + tx * 4 + u];
    }
    #pragma unroll
    for (int r = 0; r < 4; r++) {
        unsigned row = (unsigned)(bh * S + i0 + ty * 4 + r);
        #pragma unroll
        for (int u = 0; u < 4; u++) {
            float s = acc[r][u] * iq[r] * ik[u];
            unsigned bits = __float_as_uint(s);
            unsigned key = bits & 0x7fffffffu;
            unsigned idx = (row << 10) | (unsigned)(j0 + tx * 4 + u);
            unsigned val = idx | (bits & FLAG_NEG) | (key == 0u ? FLAG_ZERO : 0u);
            g_keysA[idx] = key;
            g_valsA[idx] = val;
        }
    }
}

// ---------------------------------------------------------------------------
// Stage 4: scatter rank-probabilities:  w[order[i]] = -log(i/(n-1)+1/n)*sign
// ---------------------------------------------------------------------------
__global__ void scatter_kernel(const unsigned* __restrict__ vals) {
    int i = blockIdx.x * blockDim.x + threadIdx.x;
    if (i >= N_ELE) return;
    unsigned v = vals[i];
    unsigned j = v & IDX_MASK;
    float w;
    if (v & FLAG_ZERO) {
        w = 0.0f;
    } else {
        double p = (double)i * (1.0 / (double)(N_ELE - 1));
        float prob = (float)p + 0x1p-25f;     // + 1/n (exact in fp32)
        w = -logf(prob);
        if (v & FLAG_NEG) w = -w;
    }
    g_w[j] = w;
}

// ---------------------------------------------------------------------------
// Stage 5: out = (W / rowsum(|W|)) @ V, fused (block owns full K=1024 rows)
// 64-row tile, 256 threads, 4x4 micro
// ---------------------------------------------------------------------------
__global__ void av_kernel(const float* __restrict__ V, float* __restrict__ out) {
    __shared__ float Ws[64][65];   // Ws[r][kk]
    __shared__ float Vs[64][65];   // Vs[kk][c]
    __shared__ float rsum[64];
    int bh = blockIdx.y;
    int i0 = blockIdx.x * 64;
    int tid = threadIdx.x, tx = tid & 15, ty = tid >> 4;
    const float* Wb = g_w + ((size_t)(bh * S + i0)) * S;
    const float* Vb = V + (size_t)bh * S * D;

    float acc[4][4] = {};
    float rs[4] = {};
    for (int kt = 0; kt < S; kt += 64) {
        #pragma unroll
        for (int l = 0; l < 16; l++) {
            int idx = tid + l * 256;
            int r = idx >> 6, c = idx & 63;
            Ws[r][c] = Wb[(size_t)r * S + kt + c];
            Vs[r][c] = Vb[(size_t)(kt + r) * D + c];
        }
        __syncthreads();
        #pragma unroll 8
        for (int kk = 0; kk < 64; kk++) {
            float a[4], b[4];
            #pragma unroll
            for (int u = 0; u < 4; u++) b[u] = Vs[kk][tx * 4 + u];
            #pragma unroll
            for (int r = 0; r < 4; r++) a[r] = Ws[ty * 4 + r][kk];
            if (tx == 0) {
                #pragma unroll
                for (int r = 0; r < 4; r++) rs[r] += fabsf(a[r]);
            }
            #pragma unroll
            for (int r = 0; r < 4; r++)
                #pragma unroll
                for (int u = 0; u < 4; u++)
                    acc[r][u] += a[r] * b[u];
        }
        __syncthreads();
    }
    if (tx == 0) {
        #pragma unroll
        for (int r = 0; r < 4; r++) rsum[ty * 4 + r] = rs[r];
    }
    __syncthreads();
    #pragma unroll
    for (int r = 0; r < 4; r++) {
        float inv = 1.0f / rsum[ty * 4 + r];
        size_t obase = ((size_t)(bh * S) + i0 + ty * 4 + r) * D + tx * 4;
        #pragma unroll
        for (int u = 0; u < 4; u++)
            out[obase + u] = acc[r][u] * inv;
    }
}

// ---------------------------------------------------------------------------
extern "C" void kernel_launch(void* const* d_in, const int* in_sizes, int n_in,
                              void* d_out, int out_size) {
    const float* q = (const float*)d_in[0];
    const float* k = (const float*)d_in[1];
    const float* v = (const float*)d_in[2];
    float* out = (float*)d_out;

    // Stage 1: inverse lengths
    norms_kernel<<<8192, 256>>>(q, k);

    // Stage 2: cosine scores -> keys/payloads
    dim3 g1(S / 64, S / 64, BH);
    qk_kernel<<<g1, 256>>>(q, k);

    // Stage 3: stable ascending radix sort of (abs-score bits, idx|flags)
    unsigned *kA, *kB, *vA, *vB;
    void* tmp;
    cudaGetSymbolAddress((void**)&kA, g_keysA);
    cudaGetSymbolAddress((void**)&kB, g_keysB);
    cudaGetSymbolAddress((void**)&vA, g_valsA);
    cudaGetSymbolAddress((void**)&vB, g_valsB);
    cudaGetSymbolAddress(&tmp, g_temp);

    cub::DoubleBuffer<unsigned> dkeys(kA, kB);
    cub::DoubleBuffer<unsigned> dvals(vA, vB);
    size_t temp_bytes = 0;
    cub::DeviceRadixSort::SortPairs(nullptr, temp_bytes, dkeys, dvals,
                                    (int)N_ELE, 0, 32);
    if (temp_bytes > sizeof(g_temp)) return;  // (never: static buffer is 512MB)
    cub::DeviceRadixSort::SortPairs(tmp, temp_bytes, dkeys, dvals,
                                    (int)N_ELE, 0, 32);

    // Stage 4: scatter -log(rank prob) with sign
    scatter_kernel<<<N_ELE / 256, 256>>>(dvals.Current());

    // Stage 5: row-L1-normalize + apply to V
    dim3 g2(S / 64, BH);
    av_kernel<<<g2, 256>>>(v, out);
}

// round 2
// speedup vs baseline: 3.4705x; 3.4705x over previous
#include <cuda_runtime.h>
#include <cub/cub.cuh>
#include <cstdint>

// Problem constants (B=4,H=8,S=1024,D=64)
#define BH 32
#define S 1024
#define D 64
#define N_ELE (BH * S * S)          // 33554432 = 2^25
#define SHIFT 9
#define NB (1u << (31 - SHIFT))     // 4M buckets

// Static device scratch (allocation-free rule: __device__ globals only)
__device__ float    g_score[N_ELE];      // signed cosine scores, row-major [BH*S, S]
__device__ float    g_w[N_ELE];          // final weights
__device__ unsigned g_hist[NB];          // bucket populations
__device__ unsigned g_cum[NB];           // exclusive scan of populations
__device__ float    g_wmag[NB];          // per-bucket weight magnitude
__device__ float    g_invq[BH * S];
__device__ float    g_invk[BH * S];
__device__ unsigned char g_scantemp[1u << 22];

// ---------------------------------------------------------------------------
// Stage 0: zero histogram (must be re-done every replay)
// ---------------------------------------------------------------------------
__global__ void zero_hist_kernel() {
    unsigned i = blockIdx.x * blockDim.x + threadIdx.x;
    if (i < NB) g_hist[i] = 0u;
}

// ---------------------------------------------------------------------------
// Stage 1: inverse lengths  inv = 1/(sqrt(sum sq)+1e-5), one warp per row
// ---------------------------------------------------------------------------
__global__ void norms_kernel(const float* __restrict__ q, const float* __restrict__ k) {
    int warp = (blockIdx.x * blockDim.x + threadIdx.x) >> 5;
    int lane = threadIdx.x & 31;
    if (warp >= 2 * BH * S) return;
    bool is_q = warp < BH * S;
    int row = is_q ? warp : warp - BH * S;
    const float* p = (is_q ? q : k) + (size_t)row * D;
    float v0 = p[lane], v1 = p[lane + 32];
    float s = v0 * v0 + v1 * v1;
    #pragma unroll
    for (int o = 16; o; o >>= 1) s += __shfl_xor_sync(0xffffffffu, s, o);
    if (lane == 0) (is_q ? g_invq : g_invk)[row] = 1.0f / (sqrtf(s) + 1e-5f);
}

// ---------------------------------------------------------------------------
// Stage 2: QK^T (fp32) -> signed scores + atomic bucket histogram
// 64x64 tile, 256 threads, 4x4 micro-tile, transposed smem (pitch 65)
// ---------------------------------------------------------------------------
__global__ void qk_kernel(const float* __restrict__ Q, const float* __restrict__ K) {
    __shared__ float Qs[64][65];   // Qs[d][r]
    __shared__ float Ks[64][65];   // Ks[d][c]
    int bh = blockIdx.z;
    int i0 = blockIdx.y * 64;
    int j0 = blockIdx.x * 64;
    const float* Qb = Q + ((size_t)bh * S + i0) * D;
    const float* Kb = K + ((size_t)bh * S + j0) * D;
    int tid = threadIdx.x;

    #pragma unroll
    for (int l = 0; l < 16; l++) {
        int idx = tid + l * 256;          // 0..4095
        int r = idx >> 6, d = idx & 63;
        Qs[d][r] = Qb[(size_t)r * D + d];
        Ks[d][r] = Kb[(size_t)r * D + d];
    }
    __syncthreads();

    int tx = tid & 15, ty = tid >> 4;
    float acc[4][4] = {};
    #pragma unroll 8
    for (int d = 0; d < 64; d++) {
        float a[4], b[4];
        #pragma unroll
        for (int u = 0; u < 4; u++) a[u] = Qs[d][ty * 4 + u];
        #pragma unroll
        for (int u = 0; u < 4; u++) b[u] = Ks[d][tx * 4 + u];
        #pragma unroll
        for (int r = 0; r < 4; r++)
            #pragma unroll
            for (int u = 0; u < 4; u++)
                acc[r][u] += a[r] * b[u];
    }

    float iq[4], ik[4];
    #pragma unroll
    for (int u = 0; u < 4; u++) {
        iq[u] = g_invq[bh * S + i0 + ty * 4 + u];
        ik[u] = g_invk[bh * S + j0 + tx * 4 + u];
    }
    #pragma unroll
    for (int r = 0; r < 4; r++) {
        unsigned row = (unsigned)(bh * S + i0 + ty * 4 + r);
        #pragma unroll
        for (int u = 0; u < 4; u++) {
            float s = acc[r][u] * iq[r] * ik[u];
            unsigned idx = (row << 10) | (unsigned)(j0 + tx * 4 + u);
            g_score[idx] = s;
            unsigned key = __float_as_uint(s) & 0x7fffffffu;
            atomicAdd(&g_hist[key >> SHIFT], 1u);
        }
    }
}

// ---------------------------------------------------------------------------
// Stage 4: per-bucket weight magnitude:  wmag = -log(midrank/(n-1) + 1/n)
// ---------------------------------------------------------------------------
__global__ void wmag_kernel() {
    unsigned b = blockIdx.x * blockDim.x + threadIdx.x;
    if (b >= NB) return;
    unsigned pop = g_hist[b];
    if (pop == 0u) { g_wmag[b] = 0.0f; return; }
    float rmid = (float)g_cum[b] + 0.5f * (float)(pop - 1u);
    float prob = fmaf(rmid, 1.0f / (float)(N_ELE - 1), 0x1p-25f);
    g_wmag[b] = -logf(prob);
}

// ---------------------------------------------------------------------------
// Stage 5: elementwise weights: w = sign(score) * wmag[bucket(|score|)]
// ---------------------------------------------------------------------------
__global__ void weight_kernel() {
    unsigned i = (blockIdx.x * blockDim.x + threadIdx.x) * 4u;
    float4 s4 = *reinterpret_cast<const float4*>(&g_score[i]);
    float w[4];
    float sv[4] = {s4.x, s4.y, s4.z, s4.w};
    #pragma unroll
    for (int u = 0; u < 4; u++) {
        unsigned key = __float_as_uint(sv[u]) & 0x7fffffffu;
        w[u] = (key == 0u) ? 0.0f : copysignf(g_wmag[key >> SHIFT], sv[u]);
    }
    *reinterpret_cast<float4*>(&g_w[i]) = make_float4(w[0], w[1], w[2], w[3]);
}

// ---------------------------------------------------------------------------
// Stage 6: out = (W / rowsum(|W|)) @ V, fused (block owns full K=1024 rows)
// ---------------------------------------------------------------------------
__global__ void av_kernel(const float* __restrict__ V, float* __restrict__ out) {
    __shared__ float Ws[64][65];   // Ws[r][kk]
    __shared__ float Vs[64][65];   // Vs[kk][c]
    __shared__ float rsum[64];
    int bh = blockIdx.y;
    int i0 = blockIdx.x * 64;
    int tid = threadIdx.x, tx = tid & 15, ty = tid >> 4;
    const float* Wb = g_w + ((size_t)(bh * S + i0)) * S;
    const float* Vb = V + (size_t)bh * S * D;

    float acc[4][4] = {};
    float rs[4] = {};
    for (int kt = 0; kt < S; kt += 64) {
        #pragma unroll
        for (int l = 0; l < 16; l++) {
            int idx = tid + l * 256;
            int r = idx >> 6, c = idx & 63;
            Ws[r][c] = Wb[(size_t)r * S + kt + c];
            Vs[r][c] = Vb[(size_t)(kt + r) * D + c];
        }
        __syncthreads();
        #pragma unroll 8
        for (int kk = 0; kk < 64; kk++) {
            float a[4], b[4];
            #pragma unroll
            for (int u = 0; u < 4; u++) b[u] = Vs[kk][tx * 4 + u];
            #pragma unroll
            for (int r = 0; r < 4; r++) a[r] = Ws[ty * 4 + r][kk];
            if (tx == 0) {
                #pragma unroll
                for (int r = 0; r < 4; r++) rs[r] += fabsf(a[r]);
            }
            #pragma unroll
            for (int r = 0; r < 4; r++)
                #pragma unroll
                for (int u = 0; u < 4; u++)
                    acc[r][u] += a[r] * b[u];
        }
        __syncthreads();
    }
    if (tx == 0) {
        #pragma unroll
        for (int r = 0; r < 4; r++) rsum[ty * 4 + r] = rs[r];
    }
    __syncthreads();
    #pragma unroll
    for (int r = 0; r < 4; r++) {
        float inv = 1.0f / rsum[ty * 4 + r];
        size_t obase = ((size_t)(bh * S) + i0 + ty * 4 + r) * D + tx * 4;
        #pragma unroll
        for (int u = 0; u < 4; u++)
            out[obase + u] = acc[r][u] * inv;
    }
}

// ---------------------------------------------------------------------------
extern "C" void kernel_launch(void* const* d_in, const int* in_sizes, int n_in,
                              void* d_out, int out_size) {
    const float* q = (const float*)d_in[0];
    const float* k = (const float*)d_in[1];
    const float* v = (const float*)d_in[2];
    float* out = (float*)d_out;

    // Stage 0: zero histogram
    zero_hist_kernel<<<NB / 256, 256>>>();

    // Stage 1: inverse lengths
    norms_kernel<<<8192, 256>>>(q, k);

    // Stage 2: cosine scores + bucket histogram
    dim3 g1(S / 64, S / 64, BH);
    qk_kernel<<<g1, 256>>>(q, k);

    // Stage 3: exclusive scan of bucket populations
    unsigned *hist_p, *cum_p;
    void* tmp;
    cudaGetSymbolAddress((void**)&hist_p, g_hist);
    cudaGetSymbolAddress((void**)&cum_p, g_cum);
    cudaGetSymbolAddress(&tmp, g_scantemp);
    size_t temp_bytes = 0;
    cub::DeviceScan::ExclusiveSum(nullptr, temp_bytes, hist_p, cum_p, (int)NB);
    if (temp_bytes > sizeof(g_scantemp)) return;
    cub::DeviceScan::ExclusiveSum(tmp, temp_bytes, hist_p, cum_p, (int)NB);

    // Stage 4: per-bucket weight magnitudes
    wmag_kernel<<<NB / 256, 256>>>();

    // Stage 5: elementwise weights
    weight_kernel<<<N_ELE / 1024, 256>>>();

    // Stage 6: row-L1-normalize + apply to V
    dim3 g2(S / 64, BH);
    av_kernel<<<g2, 256>>>(v, out);
}